// round 9
// baseline (speedup 1.0000x reference)
#include <cuda_runtime.h>
#include <cuda_bf16.h>
#include <math.h>
#include <cstdint>

#define M_TOT 8192
#define NS    4096
#define DDIM  256
#define INV_T 14.285714285714286f    // 1 / 0.07
#define SH2   20.60992915555662f     // log2(e) / 0.07  (prefolded exp2 scale)

#define NCTA  152                    // 1 persistent CTA per SM (GB300: 152 SMs)
#define NTILES 1056                  // sum_{I=0}^{31} (64 - 2I)

// sim kernel: 256x128 tile, K in 4 chunks of 64 cols (128 B/row), 3-stage ring
#define A_PART      (256 * 128)              // 32 KB: A chunk (256 rows x 128 B)
#define B_PART      (128 * 128)              // 16 KB: B chunk
#define STAGE_BYTES (A_PART + B_PART)        // 48 KB
#define SMEM_TOTAL  (3 * STAGE_BYTES)        // 147456 B

// Scratch (allocation-free rule: __device__ globals)
__device__ __align__(16) __nv_bfloat16 g_featb[M_TOT * DDIM];  // 4 MB
__device__ float g_acc[M_TOT];
__device__ float g_pos[NS];
__device__ unsigned g_done = 0;

// ---------------- helpers ----------------
__device__ __forceinline__ uint32_t smem_u32(const void* p) {
    uint32_t a;
    asm("{ .reg .u64 t; cvta.to.shared.u64 t, %1; cvt.u32.u64 %0, t; }" : "=r"(a) : "l"(p));
    return a;
}
#define CP16(dst, src) \
    asm volatile("cp.async.cg.shared.global [%0], [%1], 16;" :: "r"(dst), "l"(src))
#define CP_COMMIT() asm volatile("cp.async.commit_group;" ::: "memory")
#define CP_WAIT(n)  asm volatile("cp.async.wait_group %0;" :: "n"(n) : "memory")

#define LDSM4(r0, r1, r2, r3, addr) \
    asm volatile("ldmatrix.sync.aligned.m8n8.x4.shared.b16 {%0,%1,%2,%3}, [%4];" \
                 : "=r"(r0), "=r"(r1), "=r"(r2), "=r"(r3) : "r"(addr))

#define MMA16816(c0, c1, c2, c3, a0, a1, a2, a3, b0, b1) \
    asm volatile("mma.sync.aligned.m16n8k16.row.col.f32.bf16.bf16.f32 " \
                 "{%0,%1,%2,%3},{%4,%5,%6,%7},{%8,%9},{%0,%1,%2,%3};" \
                 : "+f"(c0), "+f"(c1), "+f"(c2), "+f"(c3) \
                 : "r"(a0), "r"(a1), "r"(a2), "r"(a3), "r"(b0), "r"(b1))

__device__ __forceinline__ float ex2(float x) {
    float r;
    asm("ex2.approx.ftz.f32 %0, %1;" : "=f"(r) : "f"(x));
    return r;
}

// ---------------------------------------------------------------------------
// Kernel 1: fused clean + L2-normalize + positive-pair dot (one warp per pair).
// ---------------------------------------------------------------------------
__global__ __launch_bounds__(256) void normpos_kernel(
    const float* __restrict__ z1, const float* __restrict__ z2) {
    int w = threadIdx.x >> 5, lane = threadIdx.x & 31;
    int j = blockIdx.x * 8 + w;
    const float* s1 = z1 + (size_t)j * DDIM + lane * 8;
    const float* s2 = z2 + (size_t)j * DDIM + lane * 8;
    float4 a0 = *(const float4*)s1, a1 = *(const float4*)(s1 + 4);
    float4 b0 = *(const float4*)s2, b1 = *(const float4*)(s2 + 4);
    float x1[8] = {a0.x, a0.y, a0.z, a0.w, a1.x, a1.y, a1.z, a1.w};
    float x2[8] = {b0.x, b0.y, b0.z, b0.w, b1.x, b1.y, b1.z, b1.w};
    float ss1 = 0.f, ss2 = 0.f, sd = 0.f;
#pragma unroll
    for (int i = 0; i < 8; i++) {
        if (!isfinite(x1[i])) x1[i] = 0.0f;
        if (!isfinite(x2[i])) x2[i] = 0.0f;
        ss1 = fmaf(x1[i], x1[i], ss1);
        ss2 = fmaf(x2[i], x2[i], ss2);
        sd  = fmaf(x1[i], x2[i], sd);
    }
#pragma unroll
    for (int off = 16; off; off >>= 1) {
        ss1 += __shfl_xor_sync(0xffffffffu, ss1, off);
        ss2 += __shfl_xor_sync(0xffffffffu, ss2, off);
        sd  += __shfl_xor_sync(0xffffffffu, sd, off);
    }
    float inv1 = 1.0f / fmaxf(sqrtf(ss1), 1e-12f);
    float inv2 = 1.0f / fmaxf(sqrtf(ss2), 1e-12f);
    __nv_bfloat162 o[4];
#pragma unroll
    for (int i = 0; i < 4; i++)
        o[i] = __floats2bfloat162_rn(x1[2 * i] * inv1, x1[2 * i + 1] * inv1);
    *(uint2*)(g_featb + (size_t)j * DDIM + lane * 8) = *(uint2*)&o[0];
    *(uint2*)(g_featb + (size_t)j * DDIM + lane * 8 + 4) = *(uint2*)&o[2];
#pragma unroll
    for (int i = 0; i < 4; i++)
        o[i] = __floats2bfloat162_rn(x2[2 * i] * inv2, x2[2 * i + 1] * inv2);
    *(uint2*)(g_featb + (size_t)(j + NS) * DDIM + lane * 8) = *(uint2*)&o[0];
    *(uint2*)(g_featb + (size_t)(j + NS) * DDIM + lane * 8 + 4) = *(uint2*)&o[2];
    if (lane == 0) {
        g_pos[j] = sd * inv1 * inv2;
        g_acc[j] = 0.0f;
        g_acc[j + NS] = 0.0f;
    }
}

// ---------------------------------------------------------------------------
// Kernel 2: persistent fused HMMA sim GEMM + exp + row/col sums + final loss.
// Stacked 256x128 tiles (I = 256-row block, J = 128-col block, J in [2I, 63]):
//   J==2I   : top half (2I,2I)   = diag (mask, row-only); bottom (2I+1,2I) full
//   J==2I+1 : top half skipped (pair done at J==2I);  bottom (2I+1,2I+1) diag
//   else    : both halves full (row sums + col sums via symmetry)
// 152 persistent CTAs stream all their tiles' K-chunks through a 3-stage ring.
// Warp tile 64x64 (4x2 grid), 128 fp32 accumulators/thread.
// Last CTA (arrival counter) computes the scalar loss.
// ---------------------------------------------------------------------------
__global__ __launch_bounds__(256, 1) void sim_kernel(float* __restrict__ out) {
    extern __shared__ char smem[];
    uint32_t sb = smem_u32(smem);
    int t = threadIdx.x, lane = t & 31, wid = t >> 5;
    int warp_m = wid & 3, warp_n = wid >> 2;
    int cta = blockIdx.x;

    int nt = (cta < 144) ? 7 : 6;
    int start = (cta < 144) ? cta * 7 : 1008 + (cta - 144) * 6;
    int C4 = nt * 4;

    // Decode start tile (I, J) by integer walk.
    int I = 0, rem = start;
    while (rem >= 64 - 2 * I) { rem -= 64 - 2 * I; I++; }
    int J = 2 * I + rem;

    // Per-thread cp.async offsets: 8 segs for A (2048/256), B reuses first 4.
    uint32_t doff[8]; int soff[8];
#pragma unroll
    for (int o = 0; o < 8; o++) {
        int idx = t + o * 256;
        int r = idx >> 3, seg = idx & 7;
        doff[o] = (uint32_t)(r * 128 + ((seg ^ (r & 7)) << 4));
        soff[o] = r * 512 + seg * 16;
    }

    const char* base = (const char*)g_featb;
    int lI = I, lJ = J;
    const char* lgA = base + (size_t)lI * 131072;   // 256 rows * 512 B
    const char* lgB = base + (size_t)lJ * 65536;    // 128 rows * 512 B

    // Prologue: chunks 0 and 1 of the first tile.
#pragma unroll
    for (int o = 0; o < 8; o++) CP16(sb + doff[o], lgA + soff[o]);
#pragma unroll
    for (int o = 0; o < 4; o++) CP16(sb + A_PART + doff[o], lgB + soff[o]);
    CP_COMMIT();
#pragma unroll
    for (int o = 0; o < 8; o++) CP16(sb + STAGE_BYTES + doff[o], lgA + 128 + soff[o]);
#pragma unroll
    for (int o = 0; o < 4; o++) CP16(sb + STAGE_BYTES + A_PART + doff[o], lgB + 128 + soff[o]);
    CP_COMMIT();

    float c[4][8][4];
#pragma unroll
    for (int i = 0; i < 4; i++)
#pragma unroll
        for (int j = 0; j < 8; j++)
#pragma unroll
            for (int k = 0; k < 4; k++) c[i][j][k] = 0.0f;

    int lrow = lane & 15, khalf = lane >> 4;

    for (int cc = 0; cc < C4; cc++) {
        if (cc < C4 - 1) { CP_WAIT(1); } else { CP_WAIT(0); }
        __syncthreads();

        // Prefetch chunk cc+2 into stage (cc+2)%3.
        int pf = cc + 2;
        if (pf < C4) {
            int kc = pf & 3;
            uint32_t d0 = sb + (uint32_t)((pf % 3) * STAGE_BYTES);
            const char* a = lgA + kc * 128;
            const char* b = lgB + kc * 128;
#pragma unroll
            for (int o = 0; o < 8; o++) CP16(d0 + doff[o], a + soff[o]);
#pragma unroll
            for (int o = 0; o < 4; o++) CP16(d0 + A_PART + doff[o], b + soff[o]);
            CP_COMMIT();
            if (kc == 3) {
                lJ++;
                if (lJ == 64) { lI++; lJ = 2 * lI; }
                lgA = base + (size_t)lI * 131072;
                lgB = base + (size_t)lJ * 65536;
            }
        }

        // Compute chunk cc from stage cc%3.
        {
            uint32_t abase = sb + (uint32_t)((cc % 3) * STAGE_BYTES);
            uint32_t bbase = abase + A_PART;
#pragma unroll
            for (int ks = 0; ks < 4; ks++) {
                int segk = 2 * ks + khalf;
                uint32_t a[4][4];
#pragma unroll
                for (int mi = 0; mi < 4; mi++) {
                    int r = warp_m * 64 + mi * 16 + lrow;
                    LDSM4(a[mi][0], a[mi][1], a[mi][2], a[mi][3],
                          abase + r * 128 + ((segk ^ (r & 7)) << 4));
                }
#pragma unroll
                for (int jj = 0; jj < 4; jj++) {
                    int r = warp_n * 64 + jj * 16 + lrow;
                    uint32_t b0, b1, b2, b3;
                    LDSM4(b0, b1, b2, b3, bbase + r * 128 + ((segk ^ (r & 7)) << 4));
#pragma unroll
                    for (int mi = 0; mi < 4; mi++) {
                        MMA16816(c[mi][jj*2][0], c[mi][jj*2][1], c[mi][jj*2][2], c[mi][jj*2][3],
                                 a[mi][0], a[mi][1], a[mi][2], a[mi][3], b0, b2);
                        MMA16816(c[mi][jj*2+1][0], c[mi][jj*2+1][1], c[mi][jj*2+1][2], c[mi][jj*2+1][3],
                                 a[mi][0], a[mi][1], a[mi][2], a[mi][3], b1, b3);
                    }
                }
            }
        }

        if ((cc & 3) == 3) {
            // ---- Epilogue for tile (I, J) ----
            // mode: 0 = full (row+col), 1 = diag (mask, row-only), 2 = skip
            int topmode = (J == 2 * I) ? 1 : ((J == 2 * I + 1) ? 2 : 0);
            int botmode = (J == 2 * I + 1) ? 1 : 0;
            int mode = (warp_m < 2) ? topmode : botmode;

            if (mode != 2) {
                int r0 = lane >> 2;
                int cq = (lane & 3) * 2;
                float rowsum[4][2];
                float colsum[8][2];
#pragma unroll
                for (int i = 0; i < 4; i++) { rowsum[i][0] = 0.f; rowsum[i][1] = 0.f; }
#pragma unroll
                for (int j = 0; j < 8; j++) { colsum[j][0] = 0.f; colsum[j][1] = 0.f; }

#pragma unroll
                for (int mi = 0; mi < 4; mi++) {
                    int gr = I * 256 + warp_m * 64 + mi * 16 + r0;
#pragma unroll
                    for (int j = 0; j < 8; j++) {
                        int gc = J * 128 + warp_n * 64 + j * 8 + cq;
                        float e0 = ex2(fmaf(c[mi][j][0], SH2, -SH2));
                        float e1 = ex2(fmaf(c[mi][j][1], SH2, -SH2));
                        float e2 = ex2(fmaf(c[mi][j][2], SH2, -SH2));
                        float e3 = ex2(fmaf(c[mi][j][3], SH2, -SH2));
                        if (mode == 1) {
                            if (gr == gc)         e0 = 0.0f;
                            if (gr == gc + 1)     e1 = 0.0f;
                            if (gr + 8 == gc)     e2 = 0.0f;
                            if (gr + 8 == gc + 1) e3 = 0.0f;
                        }
                        rowsum[mi][0] += e0 + e1;
                        rowsum[mi][1] += e2 + e3;
                        colsum[j][0] += e0 + e2;
                        colsum[j][1] += e1 + e3;
                    }
                }

#pragma unroll
                for (int i = 0; i < 4; i++)
#pragma unroll
                    for (int h = 0; h < 2; h++) {
                        rowsum[i][h] += __shfl_xor_sync(0xffffffffu, rowsum[i][h], 1);
                        rowsum[i][h] += __shfl_xor_sync(0xffffffffu, rowsum[i][h], 2);
                    }
                if ((lane & 3) == 0) {
#pragma unroll
                    for (int i = 0; i < 4; i++) {
                        int gr = I * 256 + warp_m * 64 + i * 16 + r0;
                        atomicAdd(&g_acc[gr], rowsum[i][0]);
                        atomicAdd(&g_acc[gr + 8], rowsum[i][1]);
                    }
                }
                if (mode == 0) {
#pragma unroll
                    for (int j = 0; j < 8; j++)
#pragma unroll
                        for (int h = 0; h < 2; h++) {
                            colsum[j][h] += __shfl_xor_sync(0xffffffffu, colsum[j][h], 4);
                            colsum[j][h] += __shfl_xor_sync(0xffffffffu, colsum[j][h], 8);
                            colsum[j][h] += __shfl_xor_sync(0xffffffffu, colsum[j][h], 16);
                        }
                    if (lane < 4) {
#pragma unroll
                        for (int j = 0; j < 8; j++) {
                            int gc = J * 128 + warp_n * 64 + j * 8 + lane * 2;
                            atomicAdd(&g_acc[gc], colsum[j][0]);
                            atomicAdd(&g_acc[gc + 1], colsum[j][1]);
                        }
                    }
                }
            }
            // advance compute cursor + reset accumulators
            J++;
            if (J == 64) { I++; J = 2 * I; }
#pragma unroll
            for (int i = 0; i < 4; i++)
#pragma unroll
                for (int j = 0; j < 8; j++)
#pragma unroll
                    for (int k = 0; k < 4; k++) c[i][j][k] = 0.0f;
        }
    }

    // ---- Grid-completion handoff: last CTA computes the loss. ----
    __threadfence();
    __syncthreads();
    __shared__ unsigned s_ticket;
    if (t == 0) s_ticket = atomicAdd(&g_done, 1u);
    __syncthreads();
    if (s_ticket == NCTA - 1) {
        float s = 0.0f;
        for (int i = t; i < M_TOT; i += 256)
            s += INV_T + __logf(g_acc[i]) - g_pos[i & (NS - 1)] * INV_T;
#pragma unroll
        for (int off = 16; off; off >>= 1)
            s += __shfl_xor_sync(0xffffffffu, s, off);
        __shared__ float ws[8];
        if (lane == 0) ws[wid] = s;
        __syncthreads();
        if (t == 0) {
            float tot = 0.0f;
#pragma unroll
            for (int k = 0; k < 8; k++) tot += ws[k];
            out[0] = tot * (1.0f / (float)M_TOT);
            g_done = 0;   // reset for graph replay determinism
        }
    }
}

// ---------------------------------------------------------------------------
extern "C" void kernel_launch(void* const* d_in, const int* in_sizes, int n_in,
                              void* d_out, int out_size) {
    (void)in_sizes; (void)n_in; (void)out_size;
    const float* z1 = (const float*)d_in[0];
    const float* z2 = (const float*)d_in[1];
    float* out = (float*)d_out;

    cudaFuncSetAttribute(sim_kernel, cudaFuncAttributeMaxDynamicSharedMemorySize, SMEM_TOTAL);

    normpos_kernel<<<NS / 8, 256>>>(z1, z2);
    sim_kernel<<<NCTA, 256, SMEM_TOTAL>>>(out);
}

// round 11
// speedup vs baseline: 1.0222x; 1.0222x over previous
#include <cuda_runtime.h>
#include <cuda_bf16.h>
#include <math.h>
#include <cstdint>

#define M_TOT 8192
#define NS    4096
#define DDIM  256
#define INV_T 14.285714285714286f    // 1 / 0.07
#define SH2   20.60992915555662f     // log2(e) / 0.07  (prefolded exp2 scale)

#define NTILE 64                      // 64 row-blocks of 128
#define NCTA  304                     // 2 per SM x 152 SMs (GB300)

// sim kernel: 128x128 tile, K in 4 chunks of 64 (128 B/row), 3-stage cp.async ring
#define CHUNK_BYTES   (128 * 128)            // one tile-chunk: 128 rows x 128 B
#define STAGE_BYTES   (2 * CHUNK_BYTES)      // A chunk + B chunk
#define SMEM_TOTAL    (3 * STAGE_BYTES)      // 98304 B

// Scratch (allocation-free rule: __device__ globals)
__device__ __align__(16) __nv_bfloat16 g_featb[M_TOT * DDIM];  // 4 MB
__device__ float g_acc[M_TOT];
__device__ float g_pos[NS];
__device__ unsigned g_done = 0;

// ---------------- helpers ----------------
__device__ __forceinline__ uint32_t smem_u32(const void* p) {
    uint32_t a;
    asm("{ .reg .u64 t; cvta.to.shared.u64 t, %1; cvt.u32.u64 %0, t; }" : "=r"(a) : "l"(p));
    return a;
}
#define CP16(dst, src) \
    asm volatile("cp.async.cg.shared.global [%0], [%1], 16;" :: "r"(dst), "l"(src))
#define CP_COMMIT() asm volatile("cp.async.commit_group;" ::: "memory")
#define CP_WAIT(n)  asm volatile("cp.async.wait_group %0;" :: "n"(n) : "memory")

#define LDSM4(r0, r1, r2, r3, addr) \
    asm volatile("ldmatrix.sync.aligned.m8n8.x4.shared.b16 {%0,%1,%2,%3}, [%4];" \
                 : "=r"(r0), "=r"(r1), "=r"(r2), "=r"(r3) : "r"(addr))

#define MMA16816(c0, c1, c2, c3, a0, a1, a2, a3, b0, b1) \
    asm volatile("mma.sync.aligned.m16n8k16.row.col.f32.bf16.bf16.f32 " \
                 "{%0,%1,%2,%3},{%4,%5,%6,%7},{%8,%9},{%0,%1,%2,%3};" \
                 : "+f"(c0), "+f"(c1), "+f"(c2), "+f"(c3) \
                 : "r"(a0), "r"(a1), "r"(a2), "r"(a3), "r"(b0), "r"(b1))

__device__ __forceinline__ float ex2(float x) {
    float r;
    asm("ex2.approx.ftz.f32 %0, %1;" : "=f"(r) : "f"(x));
    return r;
}

// ---------------------------------------------------------------------------
// Kernel 1: fused clean + L2-normalize + positive-pair dot (one warp per pair).
// ---------------------------------------------------------------------------
__global__ __launch_bounds__(256) void normpos_kernel(
    const float* __restrict__ z1, const float* __restrict__ z2) {
    int w = threadIdx.x >> 5, lane = threadIdx.x & 31;
    int j = blockIdx.x * 8 + w;
    const float* s1 = z1 + (size_t)j * DDIM + lane * 8;
    const float* s2 = z2 + (size_t)j * DDIM + lane * 8;
    float4 a0 = *(const float4*)s1, a1 = *(const float4*)(s1 + 4);
    float4 b0 = *(const float4*)s2, b1 = *(const float4*)(s2 + 4);
    float x1[8] = {a0.x, a0.y, a0.z, a0.w, a1.x, a1.y, a1.z, a1.w};
    float x2[8] = {b0.x, b0.y, b0.z, b0.w, b1.x, b1.y, b1.z, b1.w};
    float ss1 = 0.f, ss2 = 0.f, sd = 0.f;
#pragma unroll
    for (int i = 0; i < 8; i++) {
        if (!isfinite(x1[i])) x1[i] = 0.0f;
        if (!isfinite(x2[i])) x2[i] = 0.0f;
        ss1 = fmaf(x1[i], x1[i], ss1);
        ss2 = fmaf(x2[i], x2[i], ss2);
        sd  = fmaf(x1[i], x2[i], sd);
    }
#pragma unroll
    for (int off = 16; off; off >>= 1) {
        ss1 += __shfl_xor_sync(0xffffffffu, ss1, off);
        ss2 += __shfl_xor_sync(0xffffffffu, ss2, off);
        sd  += __shfl_xor_sync(0xffffffffu, sd, off);
    }
    float inv1 = 1.0f / fmaxf(sqrtf(ss1), 1e-12f);
    float inv2 = 1.0f / fmaxf(sqrtf(ss2), 1e-12f);
    __nv_bfloat162 o[4];
#pragma unroll
    for (int i = 0; i < 4; i++)
        o[i] = __floats2bfloat162_rn(x1[2 * i] * inv1, x1[2 * i + 1] * inv1);
    *(uint2*)(g_featb + (size_t)j * DDIM + lane * 8) = *(uint2*)&o[0];
    *(uint2*)(g_featb + (size_t)j * DDIM + lane * 8 + 4) = *(uint2*)&o[2];
#pragma unroll
    for (int i = 0; i < 4; i++)
        o[i] = __floats2bfloat162_rn(x2[2 * i] * inv2, x2[2 * i + 1] * inv2);
    *(uint2*)(g_featb + (size_t)(j + NS) * DDIM + lane * 8) = *(uint2*)&o[0];
    *(uint2*)(g_featb + (size_t)(j + NS) * DDIM + lane * 8 + 4) = *(uint2*)&o[2];
    if (lane == 0) {
        g_pos[j] = sd * inv1 * inv2;
        g_acc[j] = 0.0f;
        g_acc[j + NS] = 0.0f;
    }
}

// ---------------------------------------------------------------------------
// Kernel 2: persistent fused HMMA sim GEMM + exp + row/col sums + final loss.
// Round-8 structure (proven 62us): 304 persistent CTAs, 128x128 tiles,
// continuous K-chunk stream through a 3-stage cp.async ring.
// Addressing: additive swizzle (alignment-safe; matches the store formula —
// all warp rows satisfy r&7 == lane&7, so the per-ks offset is one value).
// B-LDSM double-buffer prefetch inside the chunk; fused final loss (ticket).
// ---------------------------------------------------------------------------
struct Frag { float c[2][8][4]; };

__device__ __forceinline__ void compute_chunk(
    uint32_t sb, int st, int warp_m, int warp_n, int lane, Frag& f) {
    int lrow = lane & 15, khalf = lane >> 4;
    int x7 = lrow & 7;    // == r&7 for every row this warp touches
    uint32_t abase = sb + (uint32_t)(st * STAGE_BYTES);
    uint32_t bbase = abase + CHUNK_BYTES;
    uint32_t aA0 = abase + (uint32_t)((warp_m * 32 + lrow) * 128);
    uint32_t aA1 = aA0 + 16 * 128;
    uint32_t aB[4];
#pragma unroll
    for (int jj = 0; jj < 4; jj++)
        aB[jj] = bbase + (uint32_t)((warp_n * 64 + jj * 16 + lrow) * 128);
#pragma unroll
    for (int ks = 0; ks < 4; ks++) {
        uint32_t off = (uint32_t)(((2 * ks + khalf) ^ x7) << 4);
        uint32_t a0[4], a1[4], bq[2][4];
        LDSM4(a0[0], a0[1], a0[2], a0[3], aA0 + off);
        LDSM4(a1[0], a1[1], a1[2], a1[3], aA1 + off);
        LDSM4(bq[0][0], bq[0][1], bq[0][2], bq[0][3], aB[0] + off);
#pragma unroll
        for (int jj = 0; jj < 4; jj++) {
            int cur = jj & 1, nxt = cur ^ 1;
            if (jj < 3)   // prefetch next B block while current MMAs run
                LDSM4(bq[nxt][0], bq[nxt][1], bq[nxt][2], bq[nxt][3], aB[jj + 1] + off);
            MMA16816(f.c[0][jj*2][0], f.c[0][jj*2][1], f.c[0][jj*2][2], f.c[0][jj*2][3],
                     a0[0], a0[1], a0[2], a0[3], bq[cur][0], bq[cur][2]);
            MMA16816(f.c[0][jj*2+1][0], f.c[0][jj*2+1][1], f.c[0][jj*2+1][2], f.c[0][jj*2+1][3],
                     a0[0], a0[1], a0[2], a0[3], bq[cur][1], bq[cur][3]);
            MMA16816(f.c[1][jj*2][0], f.c[1][jj*2][1], f.c[1][jj*2][2], f.c[1][jj*2][3],
                     a1[0], a1[1], a1[2], a1[3], bq[cur][0], bq[cur][2]);
            MMA16816(f.c[1][jj*2+1][0], f.c[1][jj*2+1][1], f.c[1][jj*2+1][2], f.c[1][jj*2+1][3],
                     a1[0], a1[1], a1[2], a1[3], bq[cur][1], bq[cur][3]);
        }
    }
}

__global__ __launch_bounds__(256, 2) void sim_kernel(float* __restrict__ out) {
    extern __shared__ char smem[];
    uint32_t sb = smem_u32(smem);
    int t = threadIdx.x, lane = t & 31, wid = t >> 5;
    int warp_m = wid & 3, warp_n = wid >> 2;
    int cta = blockIdx.x;

    // Contiguous tile range: first 256 CTAs get 7 tiles, rest get 6 (256*7+48*6=2080).
    int nt = 6 + (cta < 256 ? 1 : 0);
    int start = cta * 6 + (cta < 256 ? cta : 256);
    int C4 = nt * 4;

    // Decode start tile (bi, bj) by integer walk over triangle rows.
    int bi = 0, rem = start;
    while (rem >= NTILE - bi) { rem -= NTILE - bi; bi++; }
    int bj = bi + rem;

    // Per-thread load offsets (fixed): 4 x 16B segments per chunk-half.
    uint32_t doff[4]; int soff[4];
#pragma unroll
    for (int o = 0; o < 4; o++) {
        int idx = t + o * 256;
        int r = idx >> 3, seg = idx & 7;
        doff[o] = (uint32_t)(r * 128 + ((seg ^ (r & 7)) << 4));
        soff[o] = r * 512 + seg * 16;
    }

    const char* base = (const char*)g_featb;
    int lbi = bi, lbj = bj;                       // load-cursor tile
    const char* lgA = base + (size_t)lbi * 65536; // 128 rows * 512 B
    const char* lgB = base + (size_t)lbj * 65536;

    // Prologue: chunks 0 and 1 of the first tile.
#pragma unroll
    for (int o = 0; o < 4; o++) CP16(sb + doff[o], lgA + soff[o]);
#pragma unroll
    for (int o = 0; o < 4; o++) CP16(sb + CHUNK_BYTES + doff[o], lgB + soff[o]);
    CP_COMMIT();
#pragma unroll
    for (int o = 0; o < 4; o++) CP16(sb + STAGE_BYTES + doff[o], lgA + 128 + soff[o]);
#pragma unroll
    for (int o = 0; o < 4; o++) CP16(sb + STAGE_BYTES + CHUNK_BYTES + doff[o], lgB + 128 + soff[o]);
    CP_COMMIT();

    Frag f;
#pragma unroll
    for (int i = 0; i < 2; i++)
#pragma unroll
        for (int j = 0; j < 8; j++)
#pragma unroll
            for (int k = 0; k < 4; k++) f.c[i][j][k] = 0.0f;

    for (int c = 0; c < C4; c++) {
        if (c < C4 - 1) { CP_WAIT(1); } else { CP_WAIT(0); }
        __syncthreads();   // chunk c resident; all warps past compute(c-1)

        // Prefetch chunk c+2 into stage (c+2)%3 (freed by compute(c-1)).
        int pf = c + 2;
        if (pf < C4) {
            int kc = pf & 3;
            uint32_t d0 = sb + (uint32_t)((pf % 3) * STAGE_BYTES);
            const char* a = lgA + kc * 128;
            const char* b = lgB + kc * 128;
#pragma unroll
            for (int o = 0; o < 4; o++) CP16(d0 + doff[o], a + soff[o]);
#pragma unroll
            for (int o = 0; o < 4; o++) CP16(d0 + CHUNK_BYTES + doff[o], b + soff[o]);
            CP_COMMIT();
            if (kc == 3) {                      // load-cursor to next tile
                lbj++;
                if (lbj == NTILE) { lbi++; lbj = lbi; }
                lgA = base + (size_t)lbi * 65536;
                lgB = base + (size_t)lbj * 65536;
            }
        }

        compute_chunk(sb, c % 3, warp_m, warp_n, lane, f);

        if ((c & 3) == 3) {
            // ---- Epilogue for tile (bi, bj) ----
            bool diag = (bi == bj);
            int r0 = lane >> 2;
            int cq = (lane & 3) * 2;
            float rowsum[2][2] = {{0.f, 0.f}, {0.f, 0.f}};
            float colsum[8][2];
#pragma unroll
            for (int j = 0; j < 8; j++) { colsum[j][0] = 0.f; colsum[j][1] = 0.f; }

#pragma unroll
            for (int i = 0; i < 2; i++) {
                int grA = bi * 128 + warp_m * 32 + i * 16 + r0;
#pragma unroll
                for (int j = 0; j < 8; j++) {
                    int gc = bj * 128 + warp_n * 64 + j * 8 + cq;
                    float e0 = ex2(fmaf(f.c[i][j][0], SH2, -SH2));
                    float e1 = ex2(fmaf(f.c[i][j][1], SH2, -SH2));
                    float e2 = ex2(fmaf(f.c[i][j][2], SH2, -SH2));
                    float e3 = ex2(fmaf(f.c[i][j][3], SH2, -SH2));
                    if (diag) {
                        if (grA == gc)         e0 = 0.0f;
                        if (grA == gc + 1)     e1 = 0.0f;
                        if (grA + 8 == gc)     e2 = 0.0f;
                        if (grA + 8 == gc + 1) e3 = 0.0f;
                    }
                    rowsum[i][0] += e0 + e1;
                    rowsum[i][1] += e2 + e3;
                    colsum[j][0] += e0 + e2;
                    colsum[j][1] += e1 + e3;
                }
            }

#pragma unroll
            for (int i = 0; i < 2; i++)
#pragma unroll
                for (int h = 0; h < 2; h++) {
                    rowsum[i][h] += __shfl_xor_sync(0xffffffffu, rowsum[i][h], 1);
                    rowsum[i][h] += __shfl_xor_sync(0xffffffffu, rowsum[i][h], 2);
                }
            if ((lane & 3) == 0) {
#pragma unroll
                for (int i = 0; i < 2; i++) {
                    int gr = bi * 128 + warp_m * 32 + i * 16 + r0;
                    atomicAdd(&g_acc[gr], rowsum[i][0]);
                    atomicAdd(&g_acc[gr + 8], rowsum[i][1]);
                }
            }
            if (!diag) {
#pragma unroll
                for (int j = 0; j < 8; j++)
#pragma unroll
                    for (int h = 0; h < 2; h++) {
                        colsum[j][h] += __shfl_xor_sync(0xffffffffu, colsum[j][h], 4);
                        colsum[j][h] += __shfl_xor_sync(0xffffffffu, colsum[j][h], 8);
                        colsum[j][h] += __shfl_xor_sync(0xffffffffu, colsum[j][h], 16);
                    }
                if (lane < 4) {
#pragma unroll
                    for (int j = 0; j < 8; j++) {
                        int gc = bj * 128 + warp_n * 64 + j * 8 + lane * 2;
                        atomicAdd(&g_acc[gc], colsum[j][0]);
                        atomicAdd(&g_acc[gc + 1], colsum[j][1]);
                    }
                }
            }
            // advance compute cursor + reset accumulators
            bj++;
            if (bj == NTILE) { bi++; bj = bi; }
#pragma unroll
            for (int i = 0; i < 2; i++)
#pragma unroll
                for (int j = 0; j < 8; j++)
#pragma unroll
                    for (int k = 0; k < 4; k++) f.c[i][j][k] = 0.0f;
        }
    }

    // ---- Grid-completion handoff: last CTA computes the loss. ----
    __threadfence();
    __syncthreads();
    __shared__ unsigned s_ticket;
    if (t == 0) s_ticket = atomicAdd(&g_done, 1u);
    __syncthreads();
    if (s_ticket == NCTA - 1) {
        float s = 0.0f;
        for (int i = t; i < M_TOT; i += 256)
            s += INV_T + __logf(g_acc[i]) - g_pos[i & (NS - 1)] * INV_T;
#pragma unroll
        for (int off = 16; off; off >>= 1)
            s += __shfl_xor_sync(0xffffffffu, s, off);
        __shared__ float ws[8];
        if (lane == 0) ws[wid] = s;
        __syncthreads();
        if (t == 0) {
            float tot = 0.0f;
#pragma unroll
            for (int k = 0; k < 8; k++) tot += ws[k];
            out[0] = tot * (1.0f / (float)M_TOT);
            g_done = 0;   // reset for graph replay determinism
        }
    }
}

// ---------------------------------------------------------------------------
extern "C" void kernel_launch(void* const* d_in, const int* in_sizes, int n_in,
                              void* d_out, int out_size) {
    (void)in_sizes; (void)n_in; (void)out_size;
    const float* z1 = (const float*)d_in[0];
    const float* z2 = (const float*)d_in[1];
    float* out = (float*)d_out;

    cudaFuncSetAttribute(sim_kernel, cudaFuncAttributeMaxDynamicSharedMemorySize, SMEM_TOTAL);

    normpos_kernel<<<NS / 8, 256>>>(z1, z2);
    sim_kernel<<<NCTA, 256, SMEM_TOTAL>>>(out);
}